// round 15
// baseline (speedup 1.0000x reference)
#include <cuda_runtime.h>
#include <cuda_bf16.h>
#include <cstdint>

#define DIM   768
#define HS    64
#define NSEQ  4096
#define BATCH 4
#define MROWS (BATCH * NSEQ)

typedef uint32_t u32;

__device__ u32 g_qh2[MROWS * 32], g_ql2[MROWS * 32];
__device__ u32 g_kh2[MROWS * 32], g_kl2[MROWS * 32];
__device__ u32 g_vh2[MROWS * 32], g_vl2[MROWS * 32];
__device__ u32 g_vth2[BATCH * HS * (NSEQ / 2)], g_vtl2[BATCH * HS * (NSEQ / 2)];

__device__ __forceinline__ u32 packbf(float lo, float hi) {
    u32 r; asm("cvt.rn.satfinite.bf16x2.f32 %0, %1, %2;" : "=r"(r) : "f"(hi), "f"(lo)); return r;
}
__device__ __forceinline__ float bf16r(float x) { return __bfloat162float(__float2bfloat16(x)); }
__device__ __forceinline__ float ex2(float x) {
    float r; asm("ex2.approx.f32 %0, %1;" : "=f"(r) : "f"(x)); return r;
}
__device__ __forceinline__ u32 sm_u32(const void* p) {
    u32 a; asm("{ .reg .u64 t; cvta.to.shared.u64 t, %1; cvt.u32.u64 %0, t; }"
               : "=r"(a) : "l"(p)); return a;
}

__device__ __forceinline__ void mma16816(float4& d, const u32* a, u32 b0, u32 b1) {
    asm volatile("mma.sync.aligned.m16n8k16.row.col.f32.bf16.bf16.f32 "
        "{%0,%1,%2,%3}, {%4,%5,%6,%7}, {%8,%9}, {%0,%1,%2,%3};"
        : "+f"(d.x), "+f"(d.y), "+f"(d.z), "+f"(d.w)
        : "r"(a[0]), "r"(a[1]), "r"(a[2]), "r"(a[3]), "r"(b0), "r"(b1));
}

#define LDSM4(r0, r1, r2, r3, addr) \
    asm volatile("ldmatrix.sync.aligned.m8n8.x4.shared.b16 {%0,%1,%2,%3}, [%4];" \
        : "=r"(r0), "=r"(r1), "=r"(r2), "=r"(r3) : "r"(addr))

// ---------- Kernel 1: fused QKV projection, one wave (128 CTAs, 256 thr) ----
// Each CTA computes Q, K, V for the same 128 ix rows; ix conversion amortized 3x.
// Q pre-scaled by HS^-0.5 * log2(e).
#define PSTR 20

__global__ __launch_bounds__(256) void proj_tc(
    const float* __restrict__ ix, const float* __restrict__ Wk,
    const float* __restrict__ Wq, const float* __restrict__ Wv)
{
    __shared__ u32 sAh[128 * PSTR], sAl[128 * PSTR];       // ix chunk hi/lo
    __shared__ u32 sWh[3 * 64 * PSTR], sWl[3 * 64 * PSTR]; // W^T chunks x3

    const int tid = threadIdx.x, w = tid >> 5, lane = tid & 31;
    const int gid = lane >> 2, tig = lane & 3;
    const int m0 = blockIdx.x * 128;

    const float* Ws[3] = {Wq, Wk, Wv};

    float4 acc[3][8];
    #pragma unroll
    for (int wv = 0; wv < 3; ++wv)
        #pragma unroll
        for (int nt = 0; nt < 8; ++nt) acc[wv][nt] = make_float4(0.f, 0.f, 0.f, 0.f);

    for (int k0 = 0; k0 < DIM; k0 += 32) {
        __syncthreads();
        // A chunk: 128 rows x 16 pairs (done once, shared by 3 weights)
        #pragma unroll
        for (int f = tid; f < 128 * 16; f += 256) {
            int row = f >> 4, pr = f & 15;
            float2 a = *(const float2*)(ix + (size_t)(m0 + row) * DIM + k0 + 2 * pr);
            float h0 = bf16r(a.x), h1 = bf16r(a.y);
            sAh[row * PSTR + pr] = packbf(h0, h1);
            sAl[row * PSTR + pr] = packbf(a.x - h0, a.y - h1);
        }
        // W^T chunks: 3 weights x 64 n x 16 pairs, n fastest for coalescing
        #pragma unroll
        for (int f = tid; f < 3 * 64 * 16; f += 256) {
            int wv = f >> 10, rem = f & 1023;
            int n = rem & 63, kp = rem >> 6;
            const float* W = Ws[wv];
            float w0 = W[(size_t)(k0 + 2 * kp) * HS + n];
            float w1 = W[(size_t)(k0 + 2 * kp + 1) * HS + n];
            float h0 = bf16r(w0), h1 = bf16r(w1);
            sWh[(wv * 64 + n) * PSTR + kp] = packbf(h0, h1);
            sWl[(wv * 64 + n) * PSTR + kp] = packbf(w0 - h0, w1 - h1);
        }
        __syncthreads();

        #pragma unroll
        for (int s = 0; s < 2; ++s) {
            u32 Ah[4], Al[4];
            int r = w * 16;
            Ah[0] = sAh[(r + gid) * PSTR + 8 * s + tig];
            Ah[1] = sAh[(r + gid + 8) * PSTR + 8 * s + tig];
            Ah[2] = sAh[(r + gid) * PSTR + 8 * s + 4 + tig];
            Ah[3] = sAh[(r + gid + 8) * PSTR + 8 * s + 4 + tig];
            Al[0] = sAl[(r + gid) * PSTR + 8 * s + tig];
            Al[1] = sAl[(r + gid + 8) * PSTR + 8 * s + tig];
            Al[2] = sAl[(r + gid) * PSTR + 8 * s + 4 + tig];
            Al[3] = sAl[(r + gid + 8) * PSTR + 8 * s + 4 + tig];
            #pragma unroll
            for (int wv = 0; wv < 3; ++wv) {
                #pragma unroll
                for (int nt = 0; nt < 8; ++nt) {
                    int nb = (wv * 64 + 8 * nt + gid) * PSTR + 8 * s;
                    u32 bh0 = sWh[nb + tig], bh1 = sWh[nb + 4 + tig];
                    u32 bl0 = sWl[nb + tig], bl1 = sWl[nb + 4 + tig];
                    mma16816(acc[wv][nt], Ah, bh0, bh1);
                    mma16816(acc[wv][nt], Ah, bl0, bl1);
                    mma16816(acc[wv][nt], Al, bh0, bh1);
                }
            }
        }
    }

    // epilogue: split + write all 3 staging pairs
    u32* ohs[3] = {g_qh2, g_kh2, g_vh2};
    u32* ols[3] = {g_ql2, g_kl2, g_vl2};
    const float scales[3] = {0.125f * 1.4426950408889634f, 1.0f, 1.0f};
    const int row0 = m0 + w * 16 + gid;
    const int row1 = row0 + 8;
    #pragma unroll
    for (int wv = 0; wv < 3; ++wv) {
        float scale = scales[wv];
        u32* oh = ohs[wv];
        u32* ol = ols[wv];
        #pragma unroll
        for (int nt = 0; nt < 8; ++nt) {
            float4 d = acc[wv][nt];
            float x0 = d.x * scale, x1 = d.y * scale;
            float y0 = d.z * scale, y1 = d.w * scale;
            float hx0 = bf16r(x0), hx1 = bf16r(x1);
            float hy0 = bf16r(y0), hy1 = bf16r(y1);
            oh[(size_t)row0 * 32 + 4 * nt + tig] = packbf(hx0, hx1);
            ol[(size_t)row0 * 32 + 4 * nt + tig] = packbf(x0 - hx0, x1 - hx1);
            oh[(size_t)row1 * 32 + 4 * nt + tig] = packbf(hy0, hy1);
            ol[(size_t)row1 * 32 + 4 * nt + tig] = packbf(y0 - hy0, y1 - hy1);
        }
    }
}

// ---------- Kernel 1b: V transpose (unchanged) ----------
__global__ __launch_bounds__(128) void vt_kernel()
{
    __shared__ unsigned short th[64 * 66], tl[64 * 66];
    const int jb = blockIdx.x, b = blockIdx.y;
    const int tid = threadIdx.x;

    #pragma unroll
    for (int f = tid; f < 64 * 32; f += 128) {
        int r = f >> 5, c = f & 31;
        size_t src = ((size_t)(b * NSEQ + jb * 64 + r)) * 32 + c;
        *(u32*)&th[r * 66 + 2 * c] = g_vh2[src];
        *(u32*)&tl[r * 66 + 2 * c] = g_vl2[src];
    }
    __syncthreads();

    const int h = tid >> 1, half = tid & 1;
    #pragma unroll
    for (int i = 0; i < 16; ++i) {
        int j0 = half * 32 + 2 * i;
        u32 vh = (u32)th[j0 * 66 + h] | ((u32)th[(j0 + 1) * 66 + h] << 16);
        u32 vl = (u32)tl[j0 * 66 + h] | ((u32)tl[(j0 + 1) * 66 + h] << 16);
        size_t dst = ((size_t)(b * HS + h)) * (NSEQ / 2) + jb * 32 + half * 16 + i;
        g_vth2[dst] = vh;
        g_vtl2[dst] = vl;
    }
}

// ---------- Kernel 2: HMMA flash, 128 q-rows/CTA, 256 thr, one wave (R14) ----
#define KSTR 36
#define VSTR 68

__global__ __launch_bounds__(256) void flash_tc(float* __restrict__ outp)
{
    extern __shared__ __align__(16) u32 sm4[];
    u32* sKh = sm4;
    u32* sKl = sm4 + 128 * KSTR;
    u32* sVh = sm4 + 2 * 128 * KSTR;
    u32* sVl = sVh + 64 * VSTR;

    const int tid = threadIdx.x, w = tid >> 5, lane = tid & 31;
    const int gid = lane >> 2, tig = lane & 3;
    const int b = blockIdx.x >> 5, qt = blockIdx.x & 31;

    const int lrow = (((lane >> 3) & 2) << 2) + (lane & 7);
    const int lcol = ((lane >> 3) & 1) << 2;

    u32 Qh[4][4], Ql[4][4];
    {
        const u32* qh = g_qh2 + ((size_t)(b * NSEQ + qt * 128 + w * 16)) * 32;
        const u32* ql = g_ql2 + ((size_t)(b * NSEQ + qt * 128 + w * 16)) * 32;
        #pragma unroll
        for (int s = 0; s < 4; ++s) {
            Qh[s][0] = qh[(size_t)gid * 32 + 8 * s + tig];
            Qh[s][1] = qh[(size_t)(gid + 8) * 32 + 8 * s + tig];
            Qh[s][2] = qh[(size_t)gid * 32 + 8 * s + 4 + tig];
            Qh[s][3] = qh[(size_t)(gid + 8) * 32 + 8 * s + 4 + tig];
            Ql[s][0] = ql[(size_t)gid * 32 + 8 * s + tig];
            Ql[s][1] = ql[(size_t)(gid + 8) * 32 + 8 * s + tig];
            Ql[s][2] = ql[(size_t)gid * 32 + 8 * s + 4 + tig];
            Ql[s][3] = ql[(size_t)(gid + 8) * 32 + 8 * s + 4 + tig];
        }
    }

    float4 O[8];
    #pragma unroll
    for (int u = 0; u < 8; ++u) O[u] = make_float4(0.f, 0.f, 0.f, 0.f);
    float l0r = 0.f, l1r = 0.f;

    for (int kt = 0; kt < NSEQ / 128; ++kt) {
        __syncthreads();
        const uint4* Kh4 = (const uint4*)(g_kh2 + ((size_t)(b * NSEQ + kt * 128)) * 32);
        const uint4* Kl4 = (const uint4*)(g_kl2 + ((size_t)(b * NSEQ + kt * 128)) * 32);
        #pragma unroll
        for (int f = tid; f < 1024; f += 256) {
            int row = f >> 3, c = f & 7;
            *(uint4*)&sKh[row * KSTR + c * 4] = Kh4[row * 8 + c];
            *(uint4*)&sKl[row * KSTR + c * 4] = Kl4[row * 8 + c];
        }
        const uint4* Vh4 = (const uint4*)(g_vth2 + (size_t)b * HS * (NSEQ / 2));
        const uint4* Vl4 = (const uint4*)(g_vtl2 + (size_t)b * HS * (NSEQ / 2));
        #pragma unroll
        for (int f = tid; f < 1024; f += 256) {
            int h = f >> 4, c = f & 15;
            *(uint4*)&sVh[h * VSTR + c * 4] = Vh4[h * 512 + kt * 16 + c];
            *(uint4*)&sVl[h * VSTR + c * 4] = Vl4[h * 512 + kt * 16 + c];
        }
        __syncthreads();

        float4 S[16];
        #pragma unroll
        for (int t = 0; t < 16; ++t) S[t] = make_float4(0.f, 0.f, 0.f, 0.f);
        #pragma unroll
        for (int s = 0; s < 4; ++s) {
            #pragma unroll
            for (int tp = 0; tp < 8; ++tp) {
                u32 h0, h1, h2, h3, l0, l1, l2, l3;
                u32 ah = sm_u32(&sKh[(16 * tp + lrow) * KSTR + 8 * s + lcol]);
                u32 al = sm_u32(&sKl[(16 * tp + lrow) * KSTR + 8 * s + lcol]);
                LDSM4(h0, h1, h2, h3, ah);
                LDSM4(l0, l1, l2, l3, al);
                mma16816(S[2 * tp],     Qh[s], h0, h1);
                mma16816(S[2 * tp],     Qh[s], l0, l1);
                mma16816(S[2 * tp],     Ql[s], h0, h1);
                mma16816(S[2 * tp + 1], Qh[s], h2, h3);
                mma16816(S[2 * tp + 1], Qh[s], l2, l3);
                mma16816(S[2 * tp + 1], Ql[s], h2, h3);
            }
        }

        #pragma unroll
        for (int t = 0; t < 16; ++t) {
            S[t].x = ex2(S[t].x); S[t].y = ex2(S[t].y);
            S[t].z = ex2(S[t].z); S[t].w = ex2(S[t].w);
            l0r += S[t].x + S[t].y;
            l1r += S[t].z + S[t].w;
        }

        #pragma unroll
        for (int s = 0; s < 8; ++s) {
            u32 ph[4], pl[4];
            ph[0] = packbf(S[2 * s].x,     S[2 * s].y);
            ph[1] = packbf(S[2 * s].z,     S[2 * s].w);
            ph[2] = packbf(S[2 * s + 1].x, S[2 * s + 1].y);
            ph[3] = packbf(S[2 * s + 1].z, S[2 * s + 1].w);
            pl[0] = packbf(S[2 * s].x     - __uint_as_float(ph[0] << 16),
                           S[2 * s].y     - __uint_as_float(ph[0] & 0xFFFF0000u));
            pl[1] = packbf(S[2 * s].z     - __uint_as_float(ph[1] << 16),
                           S[2 * s].w     - __uint_as_float(ph[1] & 0xFFFF0000u));
            pl[2] = packbf(S[2 * s + 1].x - __uint_as_float(ph[2] << 16),
                           S[2 * s + 1].y - __uint_as_float(ph[2] & 0xFFFF0000u));
            pl[3] = packbf(S[2 * s + 1].z - __uint_as_float(ph[3] << 16),
                           S[2 * s + 1].w - __uint_as_float(ph[3] & 0xFFFF0000u));
            #pragma unroll
            for (int up = 0; up < 4; ++up) {
                u32 h0, h1, h2, h3, l0, l1, l2, l3;
                u32 ah = sm_u32(&sVh[(16 * up + lrow) * VSTR + 8 * s + lcol]);
                u32 al = sm_u32(&sVl[(16 * up + lrow) * VSTR + 8 * s + lcol]);
                LDSM4(h0, h1, h2, h3, ah);
                LDSM4(l0, l1, l2, l3, al);
                mma16816(O[2 * up],     ph, h0, h1);
                mma16816(O[2 * up],     ph, l0, l1);
                mma16816(O[2 * up],     pl, h0, h1);
                mma16816(O[2 * up + 1], ph, h2, h3);
                mma16816(O[2 * up + 1], ph, l2, l3);
                mma16816(O[2 * up + 1], pl, h2, h3);
            }
        }
    }

    l0r += __shfl_xor_sync(0xffffffffu, l0r, 1);
    l0r += __shfl_xor_sync(0xffffffffu, l0r, 2);
    l1r += __shfl_xor_sync(0xffffffffu, l1r, 1);
    l1r += __shfl_xor_sync(0xffffffffu, l1r, 2);
    float i0 = 1.f / l0r, i1 = 1.f / l1r;
    float* o0 = outp + ((size_t)(b * NSEQ + qt * 128 + w * 16 + gid)) * HS;
    float* o1 = o0 + 8 * HS;
    #pragma unroll
    for (int u = 0; u < 8; ++u) {
        *(float2*)(o0 + 8 * u + 2 * tig) = make_float2(O[u].x * i0, O[u].y * i0);
        *(float2*)(o1 + 8 * u + 2 * tig) = make_float2(O[u].z * i1, O[u].w * i1);
    }
}

// ---------------- Launch ----------------
extern "C" void kernel_launch(void* const* d_in, const int* in_sizes, int n_in,
                              void* d_out, int out_size)
{
    (void)in_sizes; (void)n_in; (void)out_size;
    const float* ix = (const float*)d_in[0];
    const float* Wk = (const float*)d_in[1];
    const float* Wq = (const float*)d_in[2];
    const float* Wv = (const float*)d_in[3];
    float* out = (float*)d_out;

    const int smem_bytes = (2 * 128 * KSTR + 2 * 64 * VSTR) * 4;  // 71680
    cudaFuncSetAttribute(flash_tc,
                         cudaFuncAttributeMaxDynamicSharedMemorySize, smem_bytes);

    proj_tc<<<MROWS / 128, 256>>>(ix, Wk, Wq, Wv);   // 128 CTAs, one wave

    dim3 vgrid(NSEQ / 64, BATCH);
    vt_kernel<<<vgrid, 128>>>();

    flash_tc<<<BATCH * (NSEQ / 128), 256, smem_bytes>>>(out);  // 128 CTAs, one wave
}

// round 16
// speedup vs baseline: 1.0890x; 1.0890x over previous
#include <cuda_runtime.h>
#include <cuda_bf16.h>
#include <cstdint>

#define DIM   768
#define HS    64
#define NSEQ  4096
#define BATCH 4
#define MROWS (BATCH * NSEQ)

typedef uint32_t u32;

__device__ u32 g_qh2[MROWS * 32], g_ql2[MROWS * 32];
__device__ u32 g_kh2[MROWS * 32], g_kl2[MROWS * 32];
__device__ u32 g_vh2[MROWS * 32], g_vl2[MROWS * 32];
__device__ u32 g_vth2[BATCH * HS * (NSEQ / 2)], g_vtl2[BATCH * HS * (NSEQ / 2)];

__device__ __forceinline__ u32 packbf(float lo, float hi) {
    u32 r; asm("cvt.rn.satfinite.bf16x2.f32 %0, %1, %2;" : "=r"(r) : "f"(hi), "f"(lo)); return r;
}
__device__ __forceinline__ float bf16r(float x) { return __bfloat162float(__float2bfloat16(x)); }
__device__ __forceinline__ float ex2(float x) {
    float r; asm("ex2.approx.f32 %0, %1;" : "=f"(r) : "f"(x)); return r;
}
__device__ __forceinline__ u32 sm_u32(const void* p) {
    u32 a; asm("{ .reg .u64 t; cvta.to.shared.u64 t, %1; cvt.u32.u64 %0, t; }"
               : "=r"(a) : "l"(p)); return a;
}
__device__ __forceinline__ void cpa16(u32 smem_dst, const void* gsrc) {
    asm volatile("cp.async.cg.shared.global [%0], [%1], 16;"
                 :: "r"(smem_dst), "l"(gsrc) : "memory");
}
#define CPA_COMMIT() asm volatile("cp.async.commit_group;" ::: "memory")
#define CPA_WAIT0()  asm volatile("cp.async.wait_group 0;" ::: "memory")

__device__ __forceinline__ void mma16816(float4& d, const u32* a, u32 b0, u32 b1) {
    asm volatile("mma.sync.aligned.m16n8k16.row.col.f32.bf16.bf16.f32 "
        "{%0,%1,%2,%3}, {%4,%5,%6,%7}, {%8,%9}, {%0,%1,%2,%3};"
        : "+f"(d.x), "+f"(d.y), "+f"(d.z), "+f"(d.w)
        : "r"(a[0]), "r"(a[1]), "r"(a[2]), "r"(a[3]), "r"(b0), "r"(b1));
}

#define LDSM4(r0, r1, r2, r3, addr) \
    asm volatile("ldmatrix.sync.aligned.m8n8.x4.shared.b16 {%0,%1,%2,%3}, [%4];" \
        : "=r"(r0), "=r"(r1), "=r"(r2), "=r"(r3) : "r"(addr))

// ---------- Kernel 1: QKV projection via HMMA (R8 exact — best measured) ----
// Q pre-scaled by HS^-0.5 * log2(e).
#define PSTR 20

__global__ __launch_bounds__(128, 3) void proj_tc(
    const float* __restrict__ ix, const float* __restrict__ Wk,
    const float* __restrict__ Wq, const float* __restrict__ Wv)
{
    __shared__ u32 sAh[128 * PSTR], sAl[128 * PSTR];
    __shared__ u32 sWh[64 * PSTR],  sWl[64 * PSTR];

    const float* W; u32 *oh, *ol; float scale;
    if (blockIdx.y == 0)      { W = Wq; oh = g_qh2; ol = g_ql2; scale = 0.125f * 1.4426950408889634f; }
    else if (blockIdx.y == 1) { W = Wk; oh = g_kh2; ol = g_kl2; scale = 1.0f; }
    else                      { W = Wv; oh = g_vh2; ol = g_vl2; scale = 1.0f; }

    const int tid = threadIdx.x, w = tid >> 5, lane = tid & 31;
    const int gid = lane >> 2, tig = lane & 3;
    const int m0 = blockIdx.x * 128;

    float4 acc[2][8];
    #pragma unroll
    for (int mt = 0; mt < 2; ++mt)
        #pragma unroll
        for (int nt = 0; nt < 8; ++nt) acc[mt][nt] = make_float4(0.f, 0.f, 0.f, 0.f);

    for (int k0 = 0; k0 < DIM; k0 += 32) {
        __syncthreads();
        #pragma unroll
        for (int f = tid; f < 128 * 16; f += 128) {
            int row = f >> 4, pr = f & 15;
            float2 a = *(const float2*)(ix + (size_t)(m0 + row) * DIM + k0 + 2 * pr);
            float h0 = bf16r(a.x), h1 = bf16r(a.y);
            sAh[row * PSTR + pr] = packbf(h0, h1);
            sAl[row * PSTR + pr] = packbf(a.x - h0, a.y - h1);
        }
        {
            int n = tid & 63, kph = tid >> 6;
            #pragma unroll
            for (int kp = kph; kp < 16; kp += 2) {
                float w0 = W[(size_t)(k0 + 2 * kp) * HS + n];
                float w1 = W[(size_t)(k0 + 2 * kp + 1) * HS + n];
                float h0 = bf16r(w0), h1 = bf16r(w1);
                sWh[n * PSTR + kp] = packbf(h0, h1);
                sWl[n * PSTR + kp] = packbf(w0 - h0, w1 - h1);
            }
        }
        __syncthreads();

        #pragma unroll
        for (int s = 0; s < 2; ++s) {
            u32 Ah[2][4], Al[2][4];
            #pragma unroll
            for (int mt = 0; mt < 2; ++mt) {
                int r = w * 32 + mt * 16;
                Ah[mt][0] = sAh[(r + gid) * PSTR + 8 * s + tig];
                Ah[mt][1] = sAh[(r + gid + 8) * PSTR + 8 * s + tig];
                Ah[mt][2] = sAh[(r + gid) * PSTR + 8 * s + 4 + tig];
                Ah[mt][3] = sAh[(r + gid + 8) * PSTR + 8 * s + 4 + tig];
                Al[mt][0] = sAl[(r + gid) * PSTR + 8 * s + tig];
                Al[mt][1] = sAl[(r + gid + 8) * PSTR + 8 * s + tig];
                Al[mt][2] = sAl[(r + gid) * PSTR + 8 * s + 4 + tig];
                Al[mt][3] = sAl[(r + gid + 8) * PSTR + 8 * s + 4 + tig];
            }
            #pragma unroll
            for (int nt = 0; nt < 8; ++nt) {
                int nb = (8 * nt + gid) * PSTR + 8 * s;
                u32 bh0 = sWh[nb + tig], bh1 = sWh[nb + 4 + tig];
                u32 bl0 = sWl[nb + tig], bl1 = sWl[nb + 4 + tig];
                #pragma unroll
                for (int mt = 0; mt < 2; ++mt) {
                    mma16816(acc[mt][nt], Ah[mt], bh0, bh1);
                    mma16816(acc[mt][nt], Ah[mt], bl0, bl1);
                    mma16816(acc[mt][nt], Al[mt], bh0, bh1);
                }
            }
        }
    }

    #pragma unroll
    for (int mt = 0; mt < 2; ++mt) {
        int row0 = m0 + w * 32 + mt * 16 + gid;
        int row1 = row0 + 8;
        #pragma unroll
        for (int nt = 0; nt < 8; ++nt) {
            float4 d = acc[mt][nt];
            float x0 = d.x * scale, x1 = d.y * scale;
            float y0 = d.z * scale, y1 = d.w * scale;
            float hx0 = bf16r(x0), hx1 = bf16r(x1);
            float hy0 = bf16r(y0), hy1 = bf16r(y1);
            oh[(size_t)row0 * 32 + 4 * nt + tig] = packbf(hx0, hx1);
            ol[(size_t)row0 * 32 + 4 * nt + tig] = packbf(x0 - hx0, x1 - hx1);
            oh[(size_t)row1 * 32 + 4 * nt + tig] = packbf(hy0, hy1);
            ol[(size_t)row1 * 32 + 4 * nt + tig] = packbf(y0 - hy0, y1 - hy1);
        }
    }
}

// ---------- Kernel 1b: V transpose (unchanged) ----------
__global__ __launch_bounds__(128) void vt_kernel()
{
    __shared__ unsigned short th[64 * 66], tl[64 * 66];
    const int jb = blockIdx.x, b = blockIdx.y;
    const int tid = threadIdx.x;

    #pragma unroll
    for (int f = tid; f < 64 * 32; f += 128) {
        int r = f >> 5, c = f & 31;
        size_t src = ((size_t)(b * NSEQ + jb * 64 + r)) * 32 + c;
        *(u32*)&th[r * 66 + 2 * c] = g_vh2[src];
        *(u32*)&tl[r * 66 + 2 * c] = g_vl2[src];
    }
    __syncthreads();

    const int h = tid >> 1, half = tid & 1;
    #pragma unroll
    for (int i = 0; i < 16; ++i) {
        int j0 = half * 32 + 2 * i;
        u32 vh = (u32)th[j0 * 66 + h] | ((u32)th[(j0 + 1) * 66 + h] << 16);
        u32 vl = (u32)tl[j0 * 66 + h] | ((u32)tl[(j0 + 1) * 66 + h] << 16);
        size_t dst = ((size_t)(b * HS + h)) * (NSEQ / 2) + jb * 32 + half * 16 + i;
        g_vth2[dst] = vh;
        g_vtl2[dst] = vl;
    }
}

// ---------- Kernel 2: HMMA flash, one wave + double-buffered cp.async ----------
#define KSTR 36
#define VSTR 68
#define BUFU (2 * 128 * KSTR + 2 * 64 * VSTR)   // 17920 u32 per buffer

__global__ __launch_bounds__(256) void flash_tc(float* __restrict__ outp)
{
    extern __shared__ __align__(16) u32 sm4[];

    const int tid = threadIdx.x, w = tid >> 5, lane = tid & 31;
    const int gid = lane >> 2, tig = lane & 3;
    const int b = blockIdx.x >> 5, qt = blockIdx.x & 31;

    const int lrow = (((lane >> 3) & 2) << 2) + (lane & 7);
    const int lcol = ((lane >> 3) & 1) << 2;

    const uint4* Kh4 = (const uint4*)(g_kh2 + (size_t)b * NSEQ * 32);
    const uint4* Kl4 = (const uint4*)(g_kl2 + (size_t)b * NSEQ * 32);
    const uint4* Vh4 = (const uint4*)(g_vth2 + (size_t)b * HS * (NSEQ / 2));
    const uint4* Vl4 = (const uint4*)(g_vtl2 + (size_t)b * HS * (NSEQ / 2));

    // async load of key tile kt into buffer p
    auto issue_tile = [&](int kt, int p) {
        u32* base = sm4 + p * BUFU;
        u32* sKh = base;
        u32* sKl = base + 128 * KSTR;
        u32* sVh = base + 2 * 128 * KSTR;
        u32* sVl = sVh + 64 * VSTR;
        #pragma unroll
        for (int f = tid; f < 2048; f += 256) {
            int pr = f >> 10, rem = f & 1023;
            int row = rem >> 3, c = rem & 7;
            u32* d = pr ? sKl : sKh;
            const uint4* s = pr ? Kl4 : Kh4;
            cpa16(sm_u32(&d[row * KSTR + c * 4]), s + (size_t)(kt * 128 + row) * 8 + c);
        }
        #pragma unroll
        for (int f = tid; f < 2048; f += 256) {
            int pr = f >> 10, rem = f & 1023;
            int h = rem >> 4, c = rem & 15;
            u32* d = pr ? sVl : sVh;
            const uint4* s = pr ? Vl4 : Vh4;
            cpa16(sm_u32(&d[h * VSTR + c * 4]), s + (size_t)h * 512 + kt * 16 + c);
        }
        CPA_COMMIT();
    };

    u32 Qh[4][4], Ql[4][4];
    {
        const u32* qh = g_qh2 + ((size_t)(b * NSEQ + qt * 128 + w * 16)) * 32;
        const u32* ql = g_ql2 + ((size_t)(b * NSEQ + qt * 128 + w * 16)) * 32;
        #pragma unroll
        for (int s = 0; s < 4; ++s) {
            Qh[s][0] = qh[(size_t)gid * 32 + 8 * s + tig];
            Qh[s][1] = qh[(size_t)(gid + 8) * 32 + 8 * s + tig];
            Qh[s][2] = qh[(size_t)gid * 32 + 8 * s + 4 + tig];
            Qh[s][3] = qh[(size_t)(gid + 8) * 32 + 8 * s + 4 + tig];
            Ql[s][0] = ql[(size_t)gid * 32 + 8 * s + tig];
            Ql[s][1] = ql[(size_t)(gid + 8) * 32 + 8 * s + tig];
            Ql[s][2] = ql[(size_t)gid * 32 + 8 * s + 4 + tig];
            Ql[s][3] = ql[(size_t)(gid + 8) * 32 + 8 * s + 4 + tig];
        }
    }

    float4 O[8];
    #pragma unroll
    for (int u = 0; u < 8; ++u) O[u] = make_float4(0.f, 0.f, 0.f, 0.f);
    float l0r = 0.f, l1r = 0.f;

    issue_tile(0, 0);

    for (int kt = 0; kt < NSEQ / 128; ++kt) {
        CPA_WAIT0();
        __syncthreads();
        if (kt + 1 < NSEQ / 128) issue_tile(kt + 1, (kt + 1) & 1);

        u32* base = sm4 + (kt & 1) * BUFU;
        u32* sKh = base;
        u32* sKl = base + 128 * KSTR;
        u32* sVh = base + 2 * 128 * KSTR;
        u32* sVl = sVh + 64 * VSTR;

        // ---- S' = Q K^T ----
        float4 S[16];
        #pragma unroll
        for (int t = 0; t < 16; ++t) S[t] = make_float4(0.f, 0.f, 0.f, 0.f);
        #pragma unroll
        for (int s = 0; s < 4; ++s) {
            #pragma unroll
            for (int tp = 0; tp < 8; ++tp) {
                u32 h0, h1, h2, h3, l0, l1, l2, l3;
                u32 ah = sm_u32(&sKh[(16 * tp + lrow) * KSTR + 8 * s + lcol]);
                u32 al = sm_u32(&sKl[(16 * tp + lrow) * KSTR + 8 * s + lcol]);
                LDSM4(h0, h1, h2, h3, ah);
                LDSM4(l0, l1, l2, l3, al);
                mma16816(S[2 * tp],     Qh[s], h0, h1);
                mma16816(S[2 * tp],     Qh[s], l0, l1);
                mma16816(S[2 * tp],     Ql[s], h0, h1);
                mma16816(S[2 * tp + 1], Qh[s], h2, h3);
                mma16816(S[2 * tp + 1], Qh[s], l2, l3);
                mma16816(S[2 * tp + 1], Ql[s], h2, h3);
            }
        }

        // ---- P = 2^(S'), local row sums ----
        #pragma unroll
        for (int t = 0; t < 16; ++t) {
            S[t].x = ex2(S[t].x); S[t].y = ex2(S[t].y);
            S[t].z = ex2(S[t].z); S[t].w = ex2(S[t].w);
            l0r += S[t].x + S[t].y;
            l1r += S[t].z + S[t].w;
        }

        // ---- O += P V ----
        #pragma unroll
        for (int s = 0; s < 8; ++s) {
            u32 ph[4], pl[4];
            ph[0] = packbf(S[2 * s].x,     S[2 * s].y);
            ph[1] = packbf(S[2 * s].z,     S[2 * s].w);
            ph[2] = packbf(S[2 * s + 1].x, S[2 * s + 1].y);
            ph[3] = packbf(S[2 * s + 1].z, S[2 * s + 1].w);
            pl[0] = packbf(S[2 * s].x     - __uint_as_float(ph[0] << 16),
                           S[2 * s].y     - __uint_as_float(ph[0] & 0xFFFF0000u));
            pl[1] = packbf(S[2 * s].z     - __uint_as_float(ph[1] << 16),
                           S[2 * s].w     - __uint_as_float(ph[1] & 0xFFFF0000u));
            pl[2] = packbf(S[2 * s + 1].x - __uint_as_float(ph[2] << 16),
                           S[2 * s + 1].y - __uint_as_float(ph[2] & 0xFFFF0000u));
            pl[3] = packbf(S[2 * s + 1].z - __uint_as_float(ph[3] << 16),
                           S[2 * s + 1].w - __uint_as_float(ph[3] & 0xFFFF0000u));
            #pragma unroll
            for (int up = 0; up < 4; ++up) {
                u32 h0, h1, h2, h3, l0, l1, l2, l3;
                u32 ah = sm_u32(&sVh[(16 * up + lrow) * VSTR + 8 * s + lcol]);
                u32 al = sm_u32(&sVl[(16 * up + lrow) * VSTR + 8 * s + lcol]);
                LDSM4(h0, h1, h2, h3, ah);
                LDSM4(l0, l1, l2, l3, al);
                mma16816(O[2 * up],     ph, h0, h1);
                mma16816(O[2 * up],     ph, l0, l1);
                mma16816(O[2 * up],     pl, h0, h1);
                mma16816(O[2 * up + 1], ph, h2, h3);
                mma16816(O[2 * up + 1], ph, l2, l3);
                mma16816(O[2 * up + 1], pl, h2, h3);
            }
        }
    }

    l0r += __shfl_xor_sync(0xffffffffu, l0r, 1);
    l0r += __shfl_xor_sync(0xffffffffu, l0r, 2);
    l1r += __shfl_xor_sync(0xffffffffu, l1r, 1);
    l1r += __shfl_xor_sync(0xffffffffu, l1r, 2);
    float i0 = 1.f / l0r, i1 = 1.f / l1r;
    float* o0 = outp + ((size_t)(b * NSEQ + qt * 128 + w * 16 + gid)) * HS;
    float* o1 = o0 + 8 * HS;
    #pragma unroll
    for (int u = 0; u < 8; ++u) {
        *(float2*)(o0 + 8 * u + 2 * tig) = make_float2(O[u].x * i0, O[u].y * i0);
        *(float2*)(o1 + 8 * u + 2 * tig) = make_float2(O[u].z * i1, O[u].w * i1);
    }
}

// ---------------- Launch ----------------
extern "C" void kernel_launch(void* const* d_in, const int* in_sizes, int n_in,
                              void* d_out, int out_size)
{
    (void)in_sizes; (void)n_in; (void)out_size;
    const float* ix = (const float*)d_in[0];
    const float* Wk = (const float*)d_in[1];
    const float* Wq = (const float*)d_in[2];
    const float* Wv = (const float*)d_in[3];
    float* out = (float*)d_out;

    const int smem_bytes = 2 * BUFU * 4;  // 143360
    cudaFuncSetAttribute(flash_tc,
                         cudaFuncAttributeMaxDynamicSharedMemorySize, smem_bytes);

    dim3 pgrid(MROWS / 128, 3);
    proj_tc<<<pgrid, 128>>>(ix, Wk, Wq, Wv);

    dim3 vgrid(NSEQ / 64, BATCH);
    vt_kernel<<<vgrid, 128>>>();

    flash_tc<<<BATCH * (NSEQ / 128), 256, smem_bytes>>>(out);  // 128 CTAs, 1 wave
}